// round 4
// baseline (speedup 1.0000x reference)
#include <cuda_runtime.h>

#define NMAX 100000
#define HDIM 64

// ---- device scratch (no allocations allowed), 16B-aligned for float4 ops ----
__device__ __align__(16) float d_deg [NMAX];
__device__ __align__(16) float d_dinv[NMAX];
__device__ __align__(16) float d_g [(size_t)NMAX * HDIM];   // dinv-scaled node features (gather source)
__device__ __align__(16) float d_S [(size_t)NMAX * HDIM];   // scatter accumulator

// buffer selectors for the GEMM kernel (resolved in DEVICE code)
#define BUF_EXT 0
#define BUF_S   1
#define BUF_G   2

// ------------------------------------------------------------------
// degree: row = concat(e0, e1) -> each directed edge bumps both ends
// NOTE: edge_index is int32 (JAX x64 disabled -> int64 request yields int32)
// ------------------------------------------------------------------
__global__ void zero_deg_kernel(int n) {
    int i = blockIdx.x * blockDim.x + threadIdx.x;
    if (i < n) d_deg[i] = 0.0f;
}

__global__ void deg_kernel(const int* __restrict__ e0,
                           const int* __restrict__ e1, int E) {
    int e = blockIdx.x * blockDim.x + threadIdx.x;
    if (e < E) {
        atomicAdd(&d_deg[__ldg(&e0[e])], 1.0f);
        atomicAdd(&d_deg[__ldg(&e1[e])], 1.0f);
    }
}

// ------------------------------------------------------------------
// edge propagate: S[u] += g[v]; S[v] += g[u]   (norm folded into g)
// 16 threads per edge, float4 per thread, vector reductions (sm_90+)
// ------------------------------------------------------------------
__global__ __launch_bounds__(256)
void edge_prop_kernel(const int* __restrict__ e0,
                      const int* __restrict__ e1, int E) {
    long long t = (long long)blockIdx.x * blockDim.x + threadIdx.x;
    int e = (int)(t >> 4);
    int c = (int)(t & 15);
    if (e >= E) return;
    int u = __ldg(&e0[e]);
    int v = __ldg(&e1[e]);
    const float4* g4 = (const float4*)d_g;
    float4*       S4 = (float4*)d_S;
    float4 gu = __ldg(&g4[(size_t)u * 16 + c]);
    float4 gv = __ldg(&g4[(size_t)v * 16 + c]);
    atomicAdd(&S4[(size_t)v * 16 + c], gu);   // vector red, no return use
    atomicAdd(&S4[(size_t)u * 16 + c], gv);
}

// ------------------------------------------------------------------
// node GEMM: out[i] = f( (maybe dinv[i]*in[i]) @ W + b ), one thread per node
// ------------------------------------------------------------------
template<int K, int IN_SRC, int OUT_DST,
         bool COMPUTE_DINV, bool SCALE_IN, bool RELU, bool SCALE_OUT, bool ZERO_IN>
__global__ __launch_bounds__(128)
void gemm_node_kernel(const float* __restrict__ ext_in,
                      float* __restrict__ ext_out,
                      const float* __restrict__ W,
                      const float* __restrict__ bias, int nn) {
    __shared__ float sW[K * HDIM];
    __shared__ float sB[HDIM];
    int tid = threadIdx.x;
    for (int idx = tid; idx < K * HDIM / 4; idx += blockDim.x)
        ((float4*)sW)[idx] = ((const float4*)W)[idx];
    if (tid < HDIM) sB[tid] = bias[tid];
    __syncthreads();

    int i = blockIdx.x * blockDim.x + tid;
    if (i >= nn) return;

    // resolve scratch buffers in device code (valid symbol addresses here)
    const float* in  = (IN_SRC == BUF_EXT) ? ext_in  : (IN_SRC == BUF_S) ? d_S : d_g;
    float*       out = (OUT_DST == BUF_EXT) ? ext_out : (OUT_DST == BUF_S) ? d_S : d_g;

    float dv = 0.0f;
    if (COMPUTE_DINV) {
        float dg = d_deg[i];
        dv = dg > 0.0f ? rsqrtf(dg) : 0.0f;
        d_dinv[i] = dv;
    } else if (SCALE_IN || SCALE_OUT) {
        dv = d_dinv[i];
    }

    float acc[HDIM];
#pragma unroll
    for (int j = 0; j < HDIM; j++) acc[j] = sB[j];

    const float4* in4 = (const float4*)(in + (size_t)i * K);
#pragma unroll 2
    for (int k4 = 0; k4 < K / 4; k4++) {
        float4 xv = __ldg(&in4[k4]);
        if (SCALE_IN) { xv.x *= dv; xv.y *= dv; xv.z *= dv; xv.w *= dv; }
        const float* w0 = &sW[(k4 * 4 + 0) * HDIM];
        const float* w1 = &sW[(k4 * 4 + 1) * HDIM];
        const float* w2 = &sW[(k4 * 4 + 2) * HDIM];
        const float* w3 = &sW[(k4 * 4 + 3) * HDIM];
#pragma unroll
        for (int j = 0; j < HDIM; j++) {
            float a = acc[j];
            a = fmaf(xv.x, w0[j], a);
            a = fmaf(xv.y, w1[j], a);
            a = fmaf(xv.z, w2[j], a);
            a = fmaf(xv.w, w3[j], a);
            acc[j] = a;
        }
    }

    float4* out4 = (float4*)(out + (size_t)i * HDIM);
#pragma unroll
    for (int j4 = 0; j4 < HDIM / 4; j4++) {
        float4 r;
        r.x = acc[j4 * 4 + 0];
        r.y = acc[j4 * 4 + 1];
        r.z = acc[j4 * 4 + 2];
        r.w = acc[j4 * 4 + 3];
        if (RELU) {
            r.x = fmaxf(r.x, 0.0f); r.y = fmaxf(r.y, 0.0f);
            r.z = fmaxf(r.z, 0.0f); r.w = fmaxf(r.w, 0.0f);
        }
        if (SCALE_OUT) { r.x *= dv; r.y *= dv; r.z *= dv; r.w *= dv; }
        out4[j4] = r;
    }

    if (ZERO_IN) {
        float4 z = make_float4(0.f, 0.f, 0.f, 0.f);
        float4* zt = (float4*)(d_S + (size_t)i * K);
#pragma unroll
        for (int k4 = 0; k4 < K / 4; k4++) zt[k4] = z;
    }
}

// ------------------------------------------------------------------
// launch
// ------------------------------------------------------------------
extern "C" void kernel_launch(void* const* d_in, const int* in_sizes, int n_in,
                              void* d_out, int out_size) {
    const float* x     = (const float*)d_in[0];
    const int*   ei    = (const int*)d_in[1];     // int32 edge indices!
    const float* W_in  = (const float*)d_in[2];
    const float* b_in  = (const float*)d_in[3];
    const float* W1    = (const float*)d_in[4];
    const float* b1    = (const float*)d_in[5];
    const float* W2    = (const float*)d_in[6];
    const float* b2    = (const float*)d_in[7];
    const float* W_out = (const float*)d_in[8];
    const float* b_out = (const float*)d_in[9];
    float* out = (float*)d_out;

    int N = in_sizes[0] / 128;   // 100000
    int E = in_sizes[1] / 2;     // 1600000
    const int* e0 = ei;
    const int* e1 = ei + E;

    int nodeBlocks = (N + 127) / 128;
    int edgeThreads = 256;
    long long totE16 = (long long)E * 16;
    int edgeBlocks = (int)((totE16 + edgeThreads - 1) / edgeThreads);

    // 1) degree
    zero_deg_kernel<<<(N + 255) / 256, 256>>>(N);
    deg_kernel<<<(E + 255) / 256, 256>>>(e0, e1, E);

    // 2) h = x @ W_in + b_in  -> d_S (temp); also compute dinv
    gemm_node_kernel<128, BUF_EXT, BUF_S, true, false, false, false, false>
        <<<nodeBlocks, 128>>>(x, nullptr, W_in, b_in, N);

    // 3) g = dinv * relu(h @ W1 + b1) -> d_g ; zero d_S
    gemm_node_kernel<64, BUF_S, BUF_G, false, false, true, true, true>
        <<<nodeBlocks, 128>>>(nullptr, nullptr, W1, b1, N);

    // 4) propagate: S[u] += g[v], S[v] += g[u]
    edge_prop_kernel<<<edgeBlocks, edgeThreads>>>(e0, e1, E);

    // 5) g = dinv * relu((dinv*S) @ W2 + b2) -> d_g ; zero d_S
    gemm_node_kernel<64, BUF_S, BUF_G, false, true, true, true, true>
        <<<nodeBlocks, 128>>>(nullptr, nullptr, W2, b2, N);

    // 6) propagate again
    edge_prop_kernel<<<edgeBlocks, edgeThreads>>>(e0, e1, E);

    // 7) out = (dinv*S) @ W_out + b_out
    gemm_node_kernel<64, BUF_S, BUF_EXT, false, true, false, false, false>
        <<<nodeBlocks, 128>>>(nullptr, out, W_out, b_out, N);
}